// round 9
// baseline (speedup 1.0000x reference)
#include <cuda_runtime.h>
#include <cuda_bf16.h>

// NearestMatcher: B rows, N=16 queries, T=8 targets.
//   tgt = (targets==0) ? 1e6 : targets
//   indices = argmin_t |pd - tgt| (first on ties); C = min_dist - sigmoid(logits)
//   labels[i] = 1 iff C_i is the stable-min among queries matched to the same target
// (== reference argsort + first-occurrence dedup; strict-< reproduces stability exactly)

#define NQ 16
#define NT 8
#define BIGV 1000000.0f

template<bool FULL>
__global__ __launch_bounds__(128, 9)
void nearest_matcher_kernel(const float4* __restrict__ lg4,
                            const float4* __restrict__ pd4,
                            const float4* __restrict__ tg4,
                            float* __restrict__ out,
                            int B)
{
    int b = blockIdx.x * blockDim.x + threadIdx.x;
    if (b >= B) return;

    // ---- targets: 2x LDG.128, sentinel nulls ----
    float4 t0 = tg4[2 * b + 0];
    float4 t1 = tg4[2 * b + 1];
    float tgt[NT] = { t0.x, t0.y, t0.z, t0.w, t1.x, t1.y, t1.z, t1.w };
#pragma unroll
    for (int t = 0; t < NT; t++)
        tgt[t] = (tgt[t] == 0.0f) ? BIGV : tgt[t];

    // ---- process queries in chunks of 4 to cap live registers ----
    float C[NQ];
    float fi[NQ];
#pragma unroll
    for (int c = 0; c < 4; c++) {
        float4 pv = pd4[4 * b + c];
        float4 lv = lg4[4 * b + c];
        float pc[4] = { pv.x, pv.y, pv.z, pv.w };
        float lc[4] = { lv.x, lv.y, lv.z, lv.w };
#pragma unroll
        for (int q = 0; q < 4; q++) {
            int n = 4 * c + q;
            float p = pc[q];
            float d[NT];
#pragma unroll
            for (int t = 0; t < NT; t++)
                d[t] = fabsf(p - tgt[t]);
            // balanced argmin tree, strict < keeps LOWER index on exact ties
            float m01 = fminf(d[0], d[1]);  float i01 = (d[1] < d[0]) ? 1.0f : 0.0f;
            float m23 = fminf(d[2], d[3]);  float i23 = (d[3] < d[2]) ? 3.0f : 2.0f;
            float m45 = fminf(d[4], d[5]);  float i45 = (d[5] < d[4]) ? 5.0f : 4.0f;
            float m67 = fminf(d[6], d[7]);  float i67 = (d[7] < d[6]) ? 7.0f : 6.0f;
            float m03 = fminf(m01, m23);    float i03 = (m23 < m01) ? i23 : i01;
            float m47 = fminf(m45, m67);    float i47 = (m67 < m45) ? i67 : i45;
            float m   = fminf(m03, m47);    fi[n] = (m47 < m03) ? i47 : i03;

            float s = __fdividef(1.0f, 1.0f + __expf(-lc[q]));
            C[n] = m - s;
        }
    }

    if (FULL) {
        // ---- indices are final: store now so STGs overlap the dedup ----
        float4* oi = reinterpret_cast<float4*>(out) + 4 * (size_t)b;
#pragma unroll
        for (int q = 0; q < 4; q++)
            oi[q] = make_float4(fi[4 * q + 0], fi[4 * q + 1],
                                fi[4 * q + 2], fi[4 * q + 3]);

        // ---- dedup via loss counters: query n's 8-bit field in cnt[n>>2].
        // Pair (i<j), same group:  Cj<Ci  -> i loses;  Cj>=Ci -> j loses
        // (tie clears the later index == stable argsort). Max 15 losses fits 8 bits.
        // FSETP.EQ + dual-dest FSETP.LT.AND + two predicated int-adds; the adds
        // alternate IMAD/IADD3 across fma+alu pipes. 4 regs -> 4 short chains.
        unsigned cnt[4] = { 0u, 0u, 0u, 0u };
#pragma unroll
        for (int i = 0; i < NQ; i++) {
#pragma unroll
            for (int j = i + 1; j < NQ; j++) {
                bool eq = (fi[i] == fi[j]);
                bool jb = (C[j] < C[i]);
                if (eq && jb)   cnt[i >> 2] += (1u << ((i & 3) * 8));
                if (eq && !jb)  cnt[j >> 2] += (1u << ((j & 3) * 8));
            }
        }

        // ---- label = (loss field == 0): LOP3 pred-out + FSEL per query ----
        float lf[NQ];
#pragma unroll
        for (int n = 0; n < NQ; n++)
            lf[n] = (cnt[n >> 2] & (0xFFu << ((n & 3) * 8))) ? 0.0f : 1.0f;

        float4* ol = reinterpret_cast<float4*>(out + (size_t)B * NQ) + 4 * (size_t)b;
#pragma unroll
        for (int q = 0; q < 4; q++)
            ol[q] = make_float4(lf[4 * q + 0], lf[4 * q + 1],
                                lf[4 * q + 2], lf[4 * q + 3]);
    } else {
        // Fallback: indices-only output as int32
        int4* oi = reinterpret_cast<int4*>(out) + 4 * (size_t)b;
#pragma unroll
        for (int q = 0; q < 4; q++)
            oi[q] = make_int4((int)fi[4 * q + 0], (int)fi[4 * q + 1],
                              (int)fi[4 * q + 2], (int)fi[4 * q + 3]);
    }
}

extern "C" void kernel_launch(void* const* d_in, const int* in_sizes, int n_in,
                              void* d_out, int out_size)
{
    // metadata order: pred_logits [B,16], pred_disp [B,16], targets [B,8]
    const float4* lg = reinterpret_cast<const float4*>(d_in[0]);
    const float4* pd = reinterpret_cast<const float4*>(d_in[1]);
    const float4* tg = reinterpret_cast<const float4*>(d_in[2]);
    int B = in_sizes[0] / NQ;

    const int threads = 128;
    const int blocks  = (B + threads - 1) / threads;

    if ((long long)out_size >= 2LL * B * NQ) {
        nearest_matcher_kernel<true><<<blocks, threads>>>(lg, pd, tg, (float*)d_out, B);
    } else {
        nearest_matcher_kernel<false><<<blocks, threads>>>(lg, pd, tg, (float*)d_out, B);
    }
}

// round 10
// speedup vs baseline: 1.1931x; 1.1931x over previous
#include <cuda_runtime.h>
#include <cuda_bf16.h>

// NearestMatcher: B rows, N=16 queries, T=8 targets.
//   tgt = (targets==0) ? 1e6 : targets
//   indices = argmin_t |pd - tgt| (first on ties)
//   C = min_dist - sigmoid(logits);  labels[i]=1 iff C_i is the stable-min of its target group
//
// This version:
//  - argmin via IMNMX on (|d| bits & ~7) | t  (fabs+mask+embed fused in one LOP3;
//    uint order == float order for non-negative; ties -> lowest t == jnp.argmin)
//  - cost key C' = min_dist + (1 - sigmoid) = C + 1 > 0  -> asuint(C') monotone
//  - per-group stable min via per-thread private 8-slot smem table of
//    W = (asuint(C') & ~15) | query_idx ; winner == table entry; ties -> lowest idx
//    (== reference argsort + first-occurrence dedup)

#define NQ 16
#define NT 8
#define BIGV 1000000.0f
#define TBL_STRIDE 9   // 9-word stride: 9 coprime to 32 -> spread bank mapping

template<bool FULL>
__global__ __launch_bounds__(128, 8)
void nearest_matcher_kernel(const float4* __restrict__ lg4,
                            const float4* __restrict__ pd4,
                            const float4* __restrict__ tg4,
                            float* __restrict__ out,
                            int B)
{
    __shared__ unsigned tbl_s[128 * TBL_STRIDE];
    unsigned* tbl = tbl_s + threadIdx.x * TBL_STRIDE;

    int b = blockIdx.x * blockDim.x + threadIdx.x;
    if (b >= B) return;

    // ---- init private group-min table ----
#pragma unroll
    for (int g = 0; g < NT; g++) tbl[g] = 0xFFFFFFFFu;

    // ---- targets: 2x LDG.128, sentinel nulls ----
    float4 t0 = tg4[2 * b + 0];
    float4 t1 = tg4[2 * b + 1];
    float tgt[NT] = { t0.x, t0.y, t0.z, t0.w, t1.x, t1.y, t1.z, t1.w };
#pragma unroll
    for (int t = 0; t < NT; t++)
        tgt[t] = (tgt[t] == 0.0f) ? BIGV : tgt[t];

    unsigned W[NQ];     // group-min keys
    unsigned gq[NQ];    // matched group per query

    // ---- queries in chunks of 4: compute, scatter-min, store indices early ----
#pragma unroll
    for (int c = 0; c < 4; c++) {
        float4 pv = pd4[4 * b + c];
        float4 lv = lg4[4 * b + c];
        float pc[4] = { pv.x, pv.y, pv.z, pv.w };
        float lc[4] = { lv.x, lv.y, lv.z, lv.w };
        float fif[4];
#pragma unroll
        for (int q = 0; q < 4; q++) {
            int n = 4 * c + q;
            float p = pc[q];

            // |p - tgt[t]| bits with 3 LSBs replaced by t:
            // one LOP3 clears sign+LSBs and ORs in t. uint order == |d| order.
            unsigned du[NT];
#pragma unroll
            for (int t = 0; t < NT; t++)
                du[t] = (__float_as_uint(p - tgt[t]) & 0x7FFFFFF8u) | (unsigned)t;

            // balanced umin tree (IMNMX.U32), depth 3; ties -> lowest t
            unsigned m01 = umin(du[0], du[1]), m23 = umin(du[2], du[3]);
            unsigned m45 = umin(du[4], du[5]), m67 = umin(du[6], du[7]);
            unsigned m03 = umin(m01, m23),     m47 = umin(m45, m67);
            unsigned dmin = umin(m03, m47);

            unsigned g = dmin & 7u;
            gq[n]  = g;
            fif[q] = (float)g;

            // C' = min_dist + (1 - sigmoid(lg)) = C + 1 > 0  (order == reference C)
            float m  = __uint_as_float(dmin);  // min_dist with 3-LSB index noise
            float s2 = __fdividef(1.0f, 1.0f + __expf(lc[q]));  // 1 - sigmoid
            float Cp = m + s2;

            // stable key: top-28 cost bits | query index; scatter-min into group slot
            unsigned w = (__float_as_uint(Cp) & 0xFFFFFFF0u) | (unsigned)n;
            W[n] = w;
            tbl[g] = umin(tbl[g], w);
        }

        if (FULL) {
            // indices are final for this chunk: store now, overlaps remaining work
            reinterpret_cast<float4*>(out)[4 * (size_t)b + c] =
                make_float4(fif[0], fif[1], fif[2], fif[3]);
        } else {
            reinterpret_cast<int4*>(out)[4 * (size_t)b + c] =
                make_int4((int)fif[0], (int)fif[1], (int)fif[2], (int)fif[3]);
        }
    }

    if (FULL) {
        // ---- labels: query n wins iff its key IS the group minimum ----
        float lf[NQ];
#pragma unroll
        for (int n = 0; n < NQ; n++)
            lf[n] = (tbl[gq[n]] == W[n]) ? 1.0f : 0.0f;

        float4* ol = reinterpret_cast<float4*>(out + (size_t)B * NQ) + 4 * (size_t)b;
#pragma unroll
        for (int q = 0; q < 4; q++)
            ol[q] = make_float4(lf[4 * q + 0], lf[4 * q + 1],
                                lf[4 * q + 2], lf[4 * q + 3]);
    }
}

extern "C" void kernel_launch(void* const* d_in, const int* in_sizes, int n_in,
                              void* d_out, int out_size)
{
    // metadata order: pred_logits [B,16], pred_disp [B,16], targets [B,8]
    const float4* lg = reinterpret_cast<const float4*>(d_in[0]);
    const float4* pd = reinterpret_cast<const float4*>(d_in[1]);
    const float4* tg = reinterpret_cast<const float4*>(d_in[2]);
    int B = in_sizes[0] / NQ;

    const int threads = 128;
    const int blocks  = (B + threads - 1) / threads;

    if ((long long)out_size >= 2LL * B * NQ) {
        nearest_matcher_kernel<true><<<blocks, threads>>>(lg, pd, tg, (float*)d_out, B);
    } else {
        nearest_matcher_kernel<false><<<blocks, threads>>>(lg, pd, tg, (float*)d_out, B);
    }
}

// round 11
// speedup vs baseline: 1.4250x; 1.1943x over previous
#include <cuda_runtime.h>
#include <cuda_bf16.h>

// NearestMatcher: B rows, N=16 queries, T=8 targets.
//   tgt = (targets==0) ? 1e6 : targets
//   indices = argmin_t |pd - tgt| (first on ties)
//   C = min_dist - sigmoid(logits); labels[i]=1 iff C_i is the stable-min of its group
//
// Dedup via per-thread private 8-slot smem group-min table of EXACT sortable-uint
// cost keys. Table layout tbl[g][128]: word index = g*128 + tid -> bank == lane
// for every g pattern => zero bank conflicts by construction. Thread-private =>
// no synchronization anywhere.

#define NQ 16
#define NT 8
#define BIGV 1000000.0f

// order-preserving float->uint bijection (exact; handles negatives)
__device__ __forceinline__ unsigned sortable(float f) {
    unsigned u = __float_as_uint(f);
    int s = ((int)u) >> 31;                 // 0 or ~0
    return u ^ ((unsigned)s | 0x80000000u); // 1 SHF + 1 LOP3
}

template<bool FULL>
__global__ __launch_bounds__(128, 8)
void nearest_matcher_kernel(const float4* __restrict__ lg4,
                            const float4* __restrict__ pd4,
                            const float4* __restrict__ tg4,
                            float* __restrict__ out,
                            int B)
{
    __shared__ unsigned tbl_s[NT][128];
    unsigned* tbl = &tbl_s[0][threadIdx.x];   // slot g lives at tbl[g*128]

    int b = blockIdx.x * blockDim.x + threadIdx.x;
    if (b >= B) return;

    // ---- init private group-min table (conflict-free STS) ----
#pragma unroll
    for (int g = 0; g < NT; g++) tbl[g * 128] = 0xFFFFFFFFu;

    // ---- targets: 2x LDG.128, sentinel nulls (exact compare to +0) ----
    float4 t0 = tg4[2 * b + 0];
    float4 t1 = tg4[2 * b + 1];
    float tgt[NT] = { t0.x, t0.y, t0.z, t0.w, t1.x, t1.y, t1.z, t1.w };
#pragma unroll
    for (int t = 0; t < NT; t++)
        tgt[t] = (tgt[t] == 0.0f) ? BIGV : tgt[t];

    unsigned K[NQ];   // exact sortable cost keys
    int      gq[NQ];  // matched group per query

    // ---- queries in chunks of 4: argmin, cost, scatter-min, store indices ----
#pragma unroll
    for (int c = 0; c < 4; c++) {
        float4 pv = pd4[4 * b + c];
        float4 lv = lg4[4 * b + c];
        float pc[4] = { pv.x, pv.y, pv.z, pv.w };
        float lc[4] = { lv.x, lv.y, lv.z, lv.w };
        int gi[4];
#pragma unroll
        for (int q = 0; q < 4; q++) {
            int n = 4 * c + q;
            float p = pc[q];
            float d[NT];
#pragma unroll
            for (int t = 0; t < NT; t++)
                d[t] = p - tgt[t];            // FADD (fma pipe); |.| folds below

            // balanced exact argmin tree: FMNMX on |d| (abs as operand modifier),
            // int index via FSETP+SEL. Strict < keeps the LOWER index on exact
            // ties at every level == jnp.argmin first-occurrence.
            float m01 = fminf(fabsf(d[0]), fabsf(d[1]));
            int   i01 = (fabsf(d[1]) < fabsf(d[0])) ? 1 : 0;
            float m23 = fminf(fabsf(d[2]), fabsf(d[3]));
            int   i23 = (fabsf(d[3]) < fabsf(d[2])) ? 3 : 2;
            float m45 = fminf(fabsf(d[4]), fabsf(d[5]));
            int   i45 = (fabsf(d[5]) < fabsf(d[4])) ? 5 : 4;
            float m67 = fminf(fabsf(d[6]), fabsf(d[7]));
            int   i67 = (fabsf(d[7]) < fabsf(d[6])) ? 7 : 6;
            float m03 = fminf(m01, m23);  int i03 = (m23 < m01) ? i23 : i01;
            float m47 = fminf(m45, m67);  int i47 = (m67 < m45) ? i67 : i45;
            float m   = fminf(m03, m47);  int g   = (m47 < m03) ? i47 : i03;

            // exact reference cost: C = min_dist - sigmoid(logit)
            float s = __fdividef(1.0f, 1.0f + __expf(-lc[q]));
            float C = m - s;

            unsigned w = sortable(C);
            K[n]  = w;
            gq[n] = g;
            gi[q] = g;
            // private scatter-min (LDS+IMNMX+STS, bank==lane, conflict-free)
            unsigned cur = tbl[g * 128];
            tbl[g * 128] = umin(cur, w);
        }

        if (FULL) {
            // indices final for this chunk: store now (overlaps remaining work)
            reinterpret_cast<float4*>(out)[4 * (size_t)b + c] =
                make_float4((float)gi[0], (float)gi[1], (float)gi[2], (float)gi[3]);
        } else {
            reinterpret_cast<int4*>(out)[4 * (size_t)b + c] =
                make_int4(gi[0], gi[1], gi[2], gi[3]);
        }
    }

    if (FULL) {
        // ---- labels: query n wins iff its key IS its group's minimum ----
        float lf[NQ];
#pragma unroll
        for (int n = 0; n < NQ; n++)
            lf[n] = (tbl[gq[n] * 128] == K[n]) ? 1.0f : 0.0f;

        float4* ol = reinterpret_cast<float4*>(out + (size_t)B * NQ) + 4 * (size_t)b;
#pragma unroll
        for (int q = 0; q < 4; q++)
            ol[q] = make_float4(lf[4 * q + 0], lf[4 * q + 1],
                                lf[4 * q + 2], lf[4 * q + 3]);
    }
}

extern "C" void kernel_launch(void* const* d_in, const int* in_sizes, int n_in,
                              void* d_out, int out_size)
{
    // metadata order: pred_logits [B,16], pred_disp [B,16], targets [B,8]
    const float4* lg = reinterpret_cast<const float4*>(d_in[0]);
    const float4* pd = reinterpret_cast<const float4*>(d_in[1]);
    const float4* tg = reinterpret_cast<const float4*>(d_in[2]);
    int B = in_sizes[0] / NQ;

    const int threads = 128;
    const int blocks  = (B + threads - 1) / threads;

    if ((long long)out_size >= 2LL * B * NQ) {
        nearest_matcher_kernel<true><<<blocks, threads>>>(lg, pd, tg, (float*)d_out, B);
    } else {
        nearest_matcher_kernel<false><<<blocks, threads>>>(lg, pd, tg, (float*)d_out, B);
    }
}